// round 3
// baseline (speedup 1.0000x reference)
#include <cuda_runtime.h>
#include <math.h>

#define BN 64
#define TT 32
#define HD 1024
#define LL 196
#define G4 4096

// ---------------- scratch ----------------------------------------------------
__device__ float g_X1[(size_t)2048 * 4096];   // x@w_ih1^T + b_ih1 + b_hh1 (32MB)
__device__ float g_h1[2][BN * HD];            // ping-pong (fixes cross-block race)
__device__ float g_h2[2][BN * HD];
__device__ float g_c1[BN * HD];
__device__ float g_c2[BN * HD];
__device__ float g_vatt[BN * HD];

__device__ __forceinline__ float sigf(float x) { return 1.0f / (1.0f + expf(-x)); }

// ---------------- init -------------------------------------------------------
__global__ void zero_state() {
    int i = blockIdx.x * blockDim.x + threadIdx.x;
    if (i < BN * HD) {
        g_h1[0][i] = 0.f; g_h1[1][i] = 0.f;
        g_h2[0][i] = 0.f; g_h2[1][i] = 0.f;
        g_c1[i] = 0.f;    g_c2[i] = 0.f;
    }
}

// ---------------- precompute X1 = emb[tok] @ w_ih1^T + b_ih1 + b_hh1 ---------
__global__ __launch_bounds__(256) void gemm_x1(
    const int* __restrict__ inp, const float* __restrict__ emb,
    const float* __restrict__ w, const float* __restrict__ b1,
    const float* __restrict__ b2)
{
    __shared__ float As[16][68];
    __shared__ float Bs[16][68];
    __shared__ int tok[64];

    const int tid = threadIdx.x;
    const int r0 = blockIdx.y * 64;
    const int c0 = blockIdx.x * 64;

    if (tid < 64) tok[tid] = inp[r0 + tid];
    __syncthreads();

    const int lr = tid >> 2;
    const int lk = (tid & 3) * 4;
    const int ty = tid >> 4;
    const int tx = tid & 15;

    float acc[4][4] = {};

    for (int kt = 0; kt < 1024; kt += 16) {
        float4 a  = *(const float4*)(emb + (size_t)tok[lr] * 1024 + kt + lk);
        float4 bv = *(const float4*)(w   + (size_t)(c0 + lr) * 1024 + kt + lk);
        As[lk + 0][lr] = a.x;  As[lk + 1][lr] = a.y;
        As[lk + 2][lr] = a.z;  As[lk + 3][lr] = a.w;
        Bs[lk + 0][lr] = bv.x; Bs[lk + 1][lr] = bv.y;
        Bs[lk + 2][lr] = bv.z; Bs[lk + 3][lr] = bv.w;
        __syncthreads();

        #pragma unroll
        for (int k = 0; k < 16; k++) {
            float4 av = *(const float4*)&As[k][ty * 4];
            float4 bw = *(const float4*)&Bs[k][tx * 4];
            float ar[4] = {av.x, av.y, av.z, av.w};
            float br[4] = {bw.x, bw.y, bw.z, bw.w};
            #pragma unroll
            for (int i = 0; i < 4; i++)
                #pragma unroll
                for (int j = 0; j < 4; j++)
                    acc[i][j] += ar[i] * br[j];
        }
        __syncthreads();
    }

    #pragma unroll
    for (int i = 0; i < 4; i++)
        #pragma unroll
        for (int j = 0; j < 4; j++) {
            int r = r0 + ty * 4 + i;
            int c = c0 + tx * 4 + j;
            g_X1[(size_t)r * 4096 + c] = acc[i][j] + b1[c] + b2[c];
        }
}

// ---------------- fused LSTM cell GEMM ---------------------------------------
// Block handles ALL 64 rows x (4 gates x 8 d-columns) for d in [d0, d0+8).
// Thread: 4 rows x 4 gates x 1 d -> 16 accumulators -> full activation in-reg.
// Reads h from *_in buffers, writes h to *_out buffers (ping-pong: no race).
// mode 1: gates = X1[t] + h1_in @ w_hh1^T                    -> h1_out, c1
// mode 2: gates = [vatt|h1_in2]@w_ih2^T + h2_in@w_hh2^T + b  -> h2_out, c2, out[t]
__global__ __launch_bounds__(128) void cell_fused(
    int mode, int t,
    const float* __restrict__ hA_in,   // mode1: h1_prev       mode2: vatt
    const float* __restrict__ hB_in,   // mode1: (unused)      mode2: h1_cur
    const float* __restrict__ hC_in,   // mode1: (unused)      mode2: h2_prev
    float* __restrict__ h_out,         // mode1: h1_cur        mode2: h2_cur
    float* __restrict__ c_state,       // c1 or c2
    const float* __restrict__ w_hh1,
    const float* __restrict__ w_ih2,
    const float* __restrict__ w_hh2,
    const float* __restrict__ b_ih2,
    const float* __restrict__ b_hh2,
    float* __restrict__ out)
{
    __shared__ float As[16][68];      // [k][row]
    __shared__ float Bs[16][36];      // [k][dd*4 + gate]

    const int tid = threadIdx.x;
    const int d0  = blockIdx.x * 8;
    const int tr  = tid >> 3;         // 0..15 -> rows 4*tr..4*tr+3
    const int td  = tid & 7;          // 0..7  -> d = d0+td

    const float* Aseg[3];
    const float* Bseg[3];
    int bstr[3];
    int nseg;

    if (mode == 1) {
        Aseg[0] = hA_in; Bseg[0] = w_hh1; bstr[0] = 1024; nseg = 1;
    } else {
        Aseg[0] = hA_in; Bseg[0] = w_ih2;        bstr[0] = 2048;
        Aseg[1] = hB_in; Bseg[1] = w_ih2 + 1024; bstr[1] = 2048;
        Aseg[2] = hC_in; Bseg[2] = w_hh2;        bstr[2] = 1024;
        nseg = 3;
    }

    const int b_row = tid >> 2;            // 0..31 : g = b_row>>3, dd = b_row&7
    const int b_kq  = tid & 3;
    const int b_g   = b_row >> 3;
    const int b_dd  = b_row & 7;

    float acc[4][4] = {};

    for (int s = 0; s < nseg; s++) {
        const float* A = Aseg[s];
        const float* B = Bseg[s];
        const size_t bs = (size_t)bstr[s];

        for (int kt = 0; kt < 1024; kt += 16) {
            #pragma unroll
            for (int u = 0; u < 2; u++) {
                int aid = tid * 2 + u;        // 0..255
                int row = aid >> 2;           // 0..63
                int kq  = aid & 3;
                float4 a = *(const float4*)(A + (size_t)row * 1024 + kt + kq * 4);
                As[kq * 4 + 0][row] = a.x;
                As[kq * 4 + 1][row] = a.y;
                As[kq * 4 + 2][row] = a.z;
                As[kq * 4 + 3][row] = a.w;
            }
            {
                int col = b_g * 1024 + d0 + b_dd;
                float4 bv = *(const float4*)(B + (size_t)col * bs + kt + b_kq * 4);
                Bs[b_kq * 4 + 0][b_dd * 4 + b_g] = bv.x;
                Bs[b_kq * 4 + 1][b_dd * 4 + b_g] = bv.y;
                Bs[b_kq * 4 + 2][b_dd * 4 + b_g] = bv.z;
                Bs[b_kq * 4 + 3][b_dd * 4 + b_g] = bv.w;
            }
            __syncthreads();

            #pragma unroll
            for (int k = 0; k < 16; k++) {
                float4 av = *(const float4*)&As[k][tr * 4];
                float4 bw = *(const float4*)&Bs[k][td * 4];
                float ar[4] = {av.x, av.y, av.z, av.w};
                float br[4] = {bw.x, bw.y, bw.z, bw.w};
                #pragma unroll
                for (int i = 0; i < 4; i++)
                    #pragma unroll
                    for (int g = 0; g < 4; g++)
                        acc[i][g] += ar[i] * br[g];
            }
            __syncthreads();
        }
    }

    // epilogue: full LSTM activation in-register
    const int d = d0 + td;
    #pragma unroll
    for (int i = 0; i < 4; i++) {
        const int n = tr * 4 + i;
        float v0, v1, v2, v3;
        if (mode == 1) {
            const float* x1 = g_X1 + (size_t)(t * 64 + n) * 4096;
            v0 = acc[i][0] + x1[d];
            v1 = acc[i][1] + x1[1024 + d];
            v2 = acc[i][2] + x1[2048 + d];
            v3 = acc[i][3] + x1[3072 + d];
        } else {
            v0 = acc[i][0] + b_ih2[d]        + b_hh2[d];
            v1 = acc[i][1] + b_ih2[1024 + d] + b_hh2[1024 + d];
            v2 = acc[i][2] + b_ih2[2048 + d] + b_hh2[2048 + d];
            v3 = acc[i][3] + b_ih2[3072 + d] + b_hh2[3072 + d];
        }
        float ig = sigf(v0);
        float fg = sigf(v1);
        float gg = tanhf(v2);
        float og = sigf(v3);
        const int idx = n * 1024 + d;
        float cn = fg * c_state[idx] + ig * gg;
        c_state[idx] = cn;
        float hn = og * tanhf(cn);
        h_out[idx] = hn;
        if (mode == 2)
            out[(size_t)(t * 64 + n) * 1024 + d] = hn;
    }
}

// ---------------- fused attention: alpha then vatt, one block per n ----------
__global__ __launch_bounds__(256) void attn_fused(const float* __restrict__ img,
                                                  const float* __restrict__ h1_cur) {
    __shared__ float sh_h[1024];
    __shared__ float sh_a[LL];

    const int n    = blockIdx.x;
    const int tid  = threadIdx.x;
    const int w    = tid >> 5;
    const int lane = tid & 31;

    *(float4*)&sh_h[tid * 4] = *(const float4*)(h1_cur + (size_t)n * 1024 + tid * 4);
    __syncthreads();

    for (int l = w; l < LL; l += 8) {
        const float* f = img + ((size_t)n * LL + l) * 1024;
        float s = 0.f;
        #pragma unroll
        for (int i = 0; i < 8; i++) {
            int d = i * 128 + lane * 4;
            float4 fv = *(const float4*)(f + d);
            s += fv.x * sh_h[d] + fv.y * sh_h[d + 1] + fv.z * sh_h[d + 2] + fv.w * sh_h[d + 3];
        }
        #pragma unroll
        for (int off = 16; off; off >>= 1)
            s += __shfl_xor_sync(0xffffffffu, s, off);
        if (lane == 0) sh_a[l] = s;
    }
    __syncthreads();

    {
        const float* f = img + (size_t)n * LL * 1024 + tid * 4;
        float4 acc = make_float4(0.f, 0.f, 0.f, 0.f);
        #pragma unroll 4
        for (int l = 0; l < LL; l++) {
            float a = sh_a[l];
            float4 fv = *(const float4*)(f + (size_t)l * 1024);
            acc.x += a * fv.x; acc.y += a * fv.y;
            acc.z += a * fv.z; acc.w += a * fv.w;
        }
        *(float4*)(g_vatt + (size_t)n * 1024 + tid * 4) = acc;
    }
}

// ---------------- launch -----------------------------------------------------
extern "C" void kernel_launch(void* const* d_in, const int* in_sizes, int n_in,
                              void* d_out, int out_size)
{
    const int*   inputs = (const int*)  d_in[0];
    const float* img    = (const float*)d_in[1];
    const float* emb    = (const float*)d_in[2];
    const float* w_ih1  = (const float*)d_in[3];
    const float* w_hh1  = (const float*)d_in[4];
    const float* b_ih1  = (const float*)d_in[5];
    const float* b_hh1  = (const float*)d_in[6];
    const float* w_ih2  = (const float*)d_in[7];
    const float* w_hh2  = (const float*)d_in[8];
    const float* b_ih2  = (const float*)d_in[9];
    const float* b_hh2  = (const float*)d_in[10];
    float* out = (float*)d_out;

    (void)in_sizes; (void)n_in; (void)out_size;

    // resolve device-global addresses once (host-side, graph-capturable)
    static float *p_h1[2] = {nullptr, nullptr}, *p_h2[2], *p_c1, *p_c2, *p_vatt;
    if (!p_h1[0]) {
        void* tmp;
        cudaGetSymbolAddress(&tmp, g_h1);   p_h1[0] = (float*)tmp; p_h1[1] = (float*)tmp + BN * HD;
        cudaGetSymbolAddress(&tmp, g_h2);   p_h2[0] = (float*)tmp; p_h2[1] = (float*)tmp + BN * HD;
        cudaGetSymbolAddress(&tmp, g_c1);   p_c1 = (float*)tmp;
        cudaGetSymbolAddress(&tmp, g_c2);   p_c2 = (float*)tmp;
        cudaGetSymbolAddress(&tmp, g_vatt); p_vatt = (float*)tmp;
    }

    zero_state<<<256, 256>>>();
    gemm_x1<<<dim3(64, 32), 256>>>(inputs, emb, w_ih1, b_ih1, b_hh1);

    for (int t = 0; t < TT; t++) {
        const int p = t & 1;        // read h from [p], write h to [1-p]
        // cell 1: reads h1[p], writes h1[1-p], c1
        cell_fused<<<128, 128>>>(1, t, p_h1[p], nullptr, nullptr,
                                 p_h1[1 - p], p_c1,
                                 w_hh1, w_ih2, w_hh2, b_ih2, b_hh2, out);
        // attention reads h1[1-p]
        attn_fused<<<64, 256>>>(img, p_h1[1 - p]);
        // cell 2: reads vatt, h1[1-p], h2[p]; writes h2[1-p], c2, out[t]
        cell_fused<<<128, 128>>>(2, t, p_vatt, p_h1[1 - p], p_h2[p],
                                 p_h2[1 - p], p_c2,
                                 w_hh1, w_ih2, w_hh2, b_ih2, b_hh2, out);
    }
}